// round 2
// baseline (speedup 1.0000x reference)
#include <cuda_runtime.h>
#include <cuda_bf16.h>

#define O_CH  256
#define C_IN  128
#define KH_N  24
#define N_IN  24
#define N_OUT 24
#define KS    5
#define VOL   (KS*KS*KS)                          // 125
#define WH_SIZE ((size_t)O_CH*N_IN*C_IN*N_OUT)    // 18,874,368
#define NWH_BLOCKS (O_CH * 72)                    // 18432 gather blocks
#define NRN_BLOCKS (O_CH * (N_OUT / 2))           // 3072 wrn blocks (2 b per block)

// ---------------------------------------------------------------------------
// Fused kernel: blocks [0, NWH_BLOCKS) do the wH gather with inline nn argmax;
// blocks [NWH_BLOCKS, NWH_BLOCKS+NRN_BLOCKS) do the trilinear wRn resample.
// ---------------------------------------------------------------------------
__global__ void __launch_bounds__(256) fused_kernel(
        const float* __restrict__ in_H,      // [24,3,3]
        const float* __restrict__ out_H,     // [24,3,3]
        const float* __restrict__ grid_H,    // [24,3,3]
        const float* __restrict__ grid_Rn,   // [3,5,5,5]
        const float* __restrict__ weight_H,  // [256,128,24]
        const float* __restrict__ weight_Rn, // [256,1,5,5,5]
        float* __restrict__ out) {
    const int idx = blockIdx.x;
    const int t = threadIdx.x;

    if (idx < NWH_BLOCKS) {
        // ---------------- wH gather path ----------------
        __shared__ int snn[N_OUT];
        const int o   = idx / 72;
        const int blk = idx % 72;
        const int a   = blk / 3;              // 3 blocks per a

        if (t < N_OUT) {
            // nn[a,t] = argmax_k <out_H[t]^T @ in_H[a], grid_H[k]>_F (first max)
            float A[9], B[9], P[9];
#pragma unroll
            for (int i = 0; i < 9; i++) {
                A[i] = in_H[a * 9 + i];
                B[i] = out_H[t * 9 + i];
            }
#pragma unroll
            for (int i = 0; i < 3; i++)
#pragma unroll
                for (int j = 0; j < 3; j++) {
                    float s = 0.f;
#pragma unroll
                    for (int k = 0; k < 3; k++) s += B[k * 3 + i] * A[k * 3 + j];
                    P[i * 3 + j] = s;
                }
            float best = -1e30f; int bi = 0;
            for (int kh = 0; kh < KH_N; kh++) {
                float s = 0.f;
#pragma unroll
                for (int i = 0; i < 9; i++) s += P[i] * grid_H[kh * 9 + i];
                if (s > best) { best = s; bi = kh; }   // strict > = first max
            }
            snn[t] = bi;
        }
        __syncthreads();

        const int tid = blk * 256 + t;        // 0..18431 within o
        const int q   = tid % 6;              // float4 slot in the 24-wide row
        const int c   = (tid / 6) % C_IN;

        const float* row = weight_H + ((size_t)o * C_IN + c) * KH_N; // 96B row
        const int b0 = q * 4;
        float4 v;
        v.x = __ldg(row + snn[b0 + 0]);
        v.y = __ldg(row + snn[b0 + 1]);
        v.z = __ldg(row + snn[b0 + 2]);
        v.w = __ldg(row + snn[b0 + 3]);

        float4* dst = reinterpret_cast<float4*>(
            out + (((size_t)o * N_IN + a) * C_IN + c) * N_OUT) + q;
        *dst = v;
    } else {
        // ---------------- wRn trilinear path ----------------
        __shared__ float vol[VOL];
        __shared__ float R[18];
        const int widx = idx - NWH_BLOCKS;
        const int o  = widx / (N_OUT / 2);
        const int bp = widx % (N_OUT / 2);    // pair of b: {2bp, 2bp+1}

        if (t < VOL) vol[t] = weight_Rn[(size_t)o * VOL + t];
        if (t < 18)  R[t]   = out_H[bp * 18 + t];
        __syncthreads();
        if (t >= 2 * VOL) return;

        const int pr = t / VOL;               // which b of the pair
        const int p  = t % VOL;
        const float* Rp = R + pr * 9;
        const int b = bp * 2 + pr;

        const float g0 = grid_Rn[p], g1 = grid_Rn[VOL + p], g2 = grid_Rn[2 * VOL + p];
        float cz = Rp[0] * g0 + Rp[3] * g1 + Rp[6] * g2;
        float cy = Rp[1] * g0 + Rp[4] * g1 + Rp[7] * g2;
        float cx = Rp[2] * g0 + Rp[5] * g1 + Rp[8] * g2;
        cz = (cz + 1.f) * 0.5f * (KS - 1);
        cy = (cy + 1.f) * 0.5f * (KS - 1);
        cx = (cx + 1.f) * 0.5f * (KS - 1);

        const float z0f = floorf(cz), y0f = floorf(cy), x0f = floorf(cx);
        const int z0 = (int)z0f, y0 = (int)y0f, x0 = (int)x0f;
        const float fz = cz - z0f, fy = cy - y0f, fx = cx - x0f;

        float acc = 0.f;
#pragma unroll
        for (int dz = 0; dz < 2; dz++)
#pragma unroll
            for (int dy = 0; dy < 2; dy++)
#pragma unroll
                for (int dx = 0; dx < 2; dx++) {
                    const int iz = z0 + dz, iy = y0 + dy, ix = x0 + dx;
                    const bool valid = (iz >= 0) & (iz < KS) & (iy >= 0) & (iy < KS)
                                     & (ix >= 0) & (ix < KS);
                    const int ci = min(max(iz, 0), KS - 1) * 25
                                 + min(max(iy, 0), KS - 1) * 5
                                 + min(max(ix, 0), KS - 1);
                    const float w = (dz ? fz : 1.f - fz) * (dy ? fy : 1.f - fy)
                                  * (dx ? fx : 1.f - fx);
                    acc += (valid ? vol[ci] : 0.f) * w;
                }

        out[WH_SIZE + ((size_t)o * N_OUT + b) * VOL + p] = acc;
    }
}

// ---------------------------------------------------------------------------
extern "C" void kernel_launch(void* const* d_in, const int* in_sizes, int n_in,
                              void* d_out, int out_size) {
    const float* in_H      = (const float*)d_in[0];
    const float* out_H     = (const float*)d_in[1];
    const float* grid_H    = (const float*)d_in[2];
    const float* grid_Rn   = (const float*)d_in[3];
    const float* weight_H  = (const float*)d_in[4];
    const float* weight_Rn = (const float*)d_in[5];
    float* out = (float*)d_out;

    fused_kernel<<<NWH_BLOCKS + NRN_BLOCKS, 256>>>(
        in_H, out_H, grid_H, grid_Rn, weight_H, weight_Rn, out);
}

// round 3
// speedup vs baseline: 1.4062x; 1.4062x over previous
#include <cuda_runtime.h>
#include <cuda_bf16.h>

#define O_CH  256
#define C_IN  128
#define KH_N  24
#define N_IN  24
#define N_OUT 24
#define KS    5
#define VOL   (KS*KS*KS)                          // 125
#define WH_SIZE ((size_t)O_CH*N_IN*C_IN*N_OUT)    // 18,874,368
#define NB_WH (O_CH * 2)                          // 512 gather blocks (half the a's each)
#define NB_RN O_CH                                // 256 wrn blocks

__device__ int g_nn[N_IN * N_OUT];

// ---------------------------------------------------------------------------
// Kernel A: nn[a,b] = argmax_k <out_H[b]^T @ in_H[a], grid_H[k]>_F (first max)
// 18 blocks x 32 threads; all operands staged in shared (no per-thread LDG storm).
// ---------------------------------------------------------------------------
__global__ void nn_kernel(const float* __restrict__ in_H,
                          const float* __restrict__ out_H,
                          const float* __restrict__ grid_H) {
    __shared__ float sIH[216], sOH[216], sGH[216];
    const int t = threadIdx.x;
    for (int i = t; i < 216; i += 32) {
        sIH[i] = in_H[i];
        sOH[i] = out_H[i];
        sGH[i] = grid_H[i];
    }
    __syncwarp();

    const int p = blockIdx.x * 32 + t;   // 0..575
    const int a = p / N_OUT, b = p % N_OUT;

    float P[9];
#pragma unroll
    for (int i = 0; i < 3; i++)
#pragma unroll
        for (int j = 0; j < 3; j++) {
            float s = 0.f;
#pragma unroll
            for (int k = 0; k < 3; k++) s += sOH[b * 9 + k * 3 + i] * sIH[a * 9 + k * 3 + j];
            P[i * 3 + j] = s;
        }
    float best = -1e30f; int bi = 0;
    for (int kh = 0; kh < KH_N; kh++) {
        float s = 0.f;
#pragma unroll
        for (int i = 0; i < 9; i++) s += P[i] * sGH[kh * 9 + i];
        if (s > best) { best = s; bi = kh; }   // strict > keeps FIRST max
    }
    g_nn[p] = bi;
}

// ---------------------------------------------------------------------------
// Kernel B (fused): blocks [0, NB_WH) = wH gather with smem-staged weights;
// blocks [NB_WH, NB_WH+NB_RN) = trilinear wRn. 1024 threads each.
// ---------------------------------------------------------------------------
__global__ void __launch_bounds__(1024) fused_kernel(
        const float* __restrict__ out_H,     // [24,3,3]
        const float* __restrict__ grid_Rn,   // [3,5,5,5]
        const float* __restrict__ weight_H,  // [256,128,24]
        const float* __restrict__ weight_Rn, // [256,1,5,5,5]
        float* __restrict__ out) {
    const int idx = blockIdx.x;
    const int t = threadIdx.x;

    if (idx < NB_WH) {
        // ---------------- wH gather ----------------
        __shared__ float sw[C_IN * KH_N];    // 12 KB: weight_H[o,:,:]
        __shared__ int   snn[N_IN * N_OUT];  // 576 nn indices
        const int o    = idx >> 1;
        const int half = idx & 1;

        const float4* wsrc = reinterpret_cast<const float4*>(
            weight_H + (size_t)o * C_IN * KH_N);
        if (t < 768) reinterpret_cast<float4*>(sw)[t] = wsrc[t];   // coalesced stage
        if (t < 576) snn[t] = g_nn[t];
        __syncthreads();

        float4* dst = reinterpret_cast<float4*>(out) + (size_t)o * 18432;
        const int base = half * 9216;        // 12 a's * 768 float4 per a
#pragma unroll
        for (int i = 0; i < 9; i++) {
            const int f = base + i * 1024 + t;
            const int a = f / 768;
            const int r = f % 768;
            const int c = r / 6, q = r % 6;
            const int* nna = snn + a * N_OUT;
            const float* row = sw + c * KH_N;
            const int b0 = q * 4;
            float4 v;
            v.x = row[nna[b0 + 0]];
            v.y = row[nna[b0 + 1]];
            v.z = row[nna[b0 + 2]];
            v.w = row[nna[b0 + 3]];
            dst[f] = v;                       // coalesced 512B/warp
        }
    } else {
        // ---------------- wRn trilinear ----------------
        __shared__ float vol[VOL];
        __shared__ float R[216];
        const int o = idx - NB_WH;
        if (t < VOL) vol[t] = weight_Rn[(size_t)o * VOL + t];
        if (t < 216) R[t]   = out_H[t];
        __syncthreads();

        for (int f = t; f < N_OUT * VOL; f += 1024) {
            const int b = f / VOL;
            const int p = f % VOL;
            const float* Rb = R + b * 9;

            const float g0 = grid_Rn[p], g1 = grid_Rn[VOL + p], g2 = grid_Rn[2 * VOL + p];
            float cz = Rb[0] * g0 + Rb[3] * g1 + Rb[6] * g2;
            float cy = Rb[1] * g0 + Rb[4] * g1 + Rb[7] * g2;
            float cx = Rb[2] * g0 + Rb[5] * g1 + Rb[8] * g2;
            cz = (cz + 1.f) * 0.5f * (KS - 1);
            cy = (cy + 1.f) * 0.5f * (KS - 1);
            cx = (cx + 1.f) * 0.5f * (KS - 1);

            const float z0f = floorf(cz), y0f = floorf(cy), x0f = floorf(cx);
            const int z0 = (int)z0f, y0 = (int)y0f, x0 = (int)x0f;
            const float fz = cz - z0f, fy = cy - y0f, fx = cx - x0f;

            float acc = 0.f;
#pragma unroll
            for (int dz = 0; dz < 2; dz++)
#pragma unroll
                for (int dy = 0; dy < 2; dy++)
#pragma unroll
                    for (int dx = 0; dx < 2; dx++) {
                        const int iz = z0 + dz, iy = y0 + dy, ix = x0 + dx;
                        const bool valid = (iz >= 0) & (iz < KS) & (iy >= 0) & (iy < KS)
                                         & (ix >= 0) & (ix < KS);
                        const int ci = min(max(iz, 0), KS - 1) * 25
                                     + min(max(iy, 0), KS - 1) * 5
                                     + min(max(ix, 0), KS - 1);
                        const float w = (dz ? fz : 1.f - fz) * (dy ? fy : 1.f - fy)
                                      * (dx ? fx : 1.f - fx);
                        acc += (valid ? vol[ci] : 0.f) * w;
                    }

            out[WH_SIZE + (size_t)o * (N_OUT * VOL) + f] = acc;
        }
    }
}

// ---------------------------------------------------------------------------
extern "C" void kernel_launch(void* const* d_in, const int* in_sizes, int n_in,
                              void* d_out, int out_size) {
    const float* in_H      = (const float*)d_in[0];
    const float* out_H     = (const float*)d_in[1];
    const float* grid_H    = (const float*)d_in[2];
    const float* grid_Rn   = (const float*)d_in[3];
    const float* weight_H  = (const float*)d_in[4];
    const float* weight_Rn = (const float*)d_in[5];
    float* out = (float*)d_out;

    nn_kernel<<<18, 32>>>(in_H, out_H, grid_H);
    fused_kernel<<<NB_WH + NB_RN, 1024>>>(out_H, grid_Rn, weight_H, weight_Rn, out);
}

// round 4
// speedup vs baseline: 1.8451x; 1.3121x over previous
#include <cuda_runtime.h>
#include <cuda_bf16.h>

#define O_CH  256
#define C_IN  128
#define KH_N  24
#define N_IN  24
#define N_OUT 24
#define KS    5
#define VOL   (KS*KS*KS)                          // 125
#define WH_SIZE ((size_t)O_CH*N_IN*C_IN*N_OUT)    // 18,874,368
#define SW_STRIDE 28                              // padded smem row stride (floats)
#define NB_WH (O_CH * 8)                          // 2048 gather blocks (3 a's each)
#define NB_RN O_CH                                // 256 wrn blocks

__device__ int g_nn[N_IN * N_OUT];

// ---------------------------------------------------------------------------
// Kernel A: nn[a,b] = argmax_k <out_H[b]^T @ in_H[a], grid_H[k]>_F (first max)
// 18 blocks x 32 threads; operands staged in shared.
// ---------------------------------------------------------------------------
__global__ void nn_kernel(const float* __restrict__ in_H,
                          const float* __restrict__ out_H,
                          const float* __restrict__ grid_H) {
    __shared__ float sIH[216], sOH[216], sGH[216];
    const int t = threadIdx.x;
    for (int i = t; i < 216; i += 32) {
        sIH[i] = in_H[i];
        sOH[i] = out_H[i];
        sGH[i] = grid_H[i];
    }
    __syncwarp();

    const int p = blockIdx.x * 32 + t;   // 0..575
    const int a = p / N_OUT, b = p % N_OUT;

    float P[9];
#pragma unroll
    for (int i = 0; i < 3; i++)
#pragma unroll
        for (int j = 0; j < 3; j++) {
            float s = 0.f;
#pragma unroll
            for (int k = 0; k < 3; k++) s += sOH[b * 9 + k * 3 + i] * sIH[a * 9 + k * 3 + j];
            P[i * 3 + j] = s;
        }
    float best = -1e30f; int bi = 0;
    for (int kh = 0; kh < KH_N; kh++) {
        float s = 0.f;
#pragma unroll
        for (int i = 0; i < 9; i++) s += P[i] * sGH[kh * 9 + i];
        if (s > best) { best = s; bi = kh; }   // strict > keeps FIRST max
    }
    g_nn[p] = bi;
}

// ---------------------------------------------------------------------------
// Fused kernel: blocks [0, NB_WH) = wH gather; [NB_WH, NB_WH+NB_RN) = wRn.
// 256 threads per block.
// ---------------------------------------------------------------------------
__global__ void __launch_bounds__(256) fused_kernel(
        const float* __restrict__ out_H,     // [24,3,3]
        const float* __restrict__ grid_Rn,   // [3,5,5,5]
        const float* __restrict__ weight_H,  // [256,128,24]
        const float* __restrict__ weight_Rn, // [256,1,5,5,5]
        float* __restrict__ out) {
    const int idx = blockIdx.x;
    const int t = threadIdx.x;

    if (idx < NB_WH) {
        // ---------------- wH gather ----------------
        __shared__ float sw[C_IN * SW_STRIDE];          // 14 KB padded weights
        __shared__ __align__(16) int snn[3 * N_OUT];    // 72 nn indices (a-local)
        const int o  = idx >> 3;
        const int a0 = (idx & 7) * 3;

        // stage weight_H[o] with padded stride (aligned float4 STS)
        const float4* wsrc = reinterpret_cast<const float4*>(
            weight_H + (size_t)o * C_IN * KH_N);
#pragma unroll
        for (int j = t; j < 768; j += 256) {
            const int c = j / 6, q = j % 6;
            *reinterpret_cast<float4*>(sw + c * SW_STRIDE + q * 4) = wsrc[j];
        }
        if (t < 72) snn[t] = g_nn[(a0 + t / N_OUT) * N_OUT + (t % N_OUT)];
        __syncthreads();

        const int4* snn4 = reinterpret_cast<const int4*>(snn);
        float4* dst = reinterpret_cast<float4*>(out)
                    + (size_t)o * 18432 + (size_t)a0 * 768;

#pragma unroll
        for (int i = 0; i < 3; i++) {
            const int j = i * 256 + t;        // float4 index within one a (0..767)
            const int c = j / 6, q = j % 6;
            const float* row = sw + c * SW_STRIDE;
#pragma unroll
            for (int al = 0; al < 3; al++) {
                const int4 nn4 = snn4[al * 6 + q];
                float4 v;
                v.x = row[nn4.x];
                v.y = row[nn4.y];
                v.z = row[nn4.z];
                v.w = row[nn4.w];
                __stcs(dst + al * 768 + j, v);  // streaming store
            }
        }
    } else {
        // ---------------- wRn trilinear ----------------
        __shared__ float vol[VOL];
        __shared__ float R[216];
        __shared__ float sg[3 * VOL];
        const int o = idx - NB_WH;
        if (t < VOL) vol[t] = weight_Rn[(size_t)o * VOL + t];
        if (t < 216) R[t]   = out_H[t];
        for (int i = t; i < 3 * VOL; i += 256) sg[i] = grid_Rn[i];
        __syncthreads();

#pragma unroll
        for (int f = t; f < N_OUT * VOL; f += 256) {
            const int b = f / VOL;
            const int p = f % VOL;
            const float* Rb = R + b * 9;

            const float g0 = sg[p], g1 = sg[VOL + p], g2 = sg[2 * VOL + p];
            float cz = Rb[0] * g0 + Rb[3] * g1 + Rb[6] * g2;
            float cy = Rb[1] * g0 + Rb[4] * g1 + Rb[7] * g2;
            float cx = Rb[2] * g0 + Rb[5] * g1 + Rb[8] * g2;
            cz = (cz + 1.f) * 0.5f * (KS - 1);
            cy = (cy + 1.f) * 0.5f * (KS - 1);
            cx = (cx + 1.f) * 0.5f * (KS - 1);

            const float z0f = floorf(cz), y0f = floorf(cy), x0f = floorf(cx);
            const int z0 = (int)z0f, y0 = (int)y0f, x0 = (int)x0f;
            const float fz = cz - z0f, fy = cy - y0f, fx = cx - x0f;

            float acc = 0.f;
#pragma unroll
            for (int dz = 0; dz < 2; dz++)
#pragma unroll
                for (int dy = 0; dy < 2; dy++)
#pragma unroll
                    for (int dx = 0; dx < 2; dx++) {
                        const int iz = z0 + dz, iy = y0 + dy, ix = x0 + dx;
                        const bool valid = (iz >= 0) & (iz < KS) & (iy >= 0) & (iy < KS)
                                         & (ix >= 0) & (ix < KS);
                        const int ci = min(max(iz, 0), KS - 1) * 25
                                     + min(max(iy, 0), KS - 1) * 5
                                     + min(max(ix, 0), KS - 1);
                        const float w = (dz ? fz : 1.f - fz) * (dy ? fy : 1.f - fy)
                                      * (dx ? fx : 1.f - fx);
                        acc += (valid ? vol[ci] : 0.f) * w;
                    }

            out[WH_SIZE + (size_t)o * (N_OUT * VOL) + f] = acc;
        }
    }
}

// ---------------------------------------------------------------------------
extern "C" void kernel_launch(void* const* d_in, const int* in_sizes, int n_in,
                              void* d_out, int out_size) {
    const float* in_H      = (const float*)d_in[0];
    const float* out_H     = (const float*)d_in[1];
    const float* grid_H    = (const float*)d_in[2];
    const float* grid_Rn   = (const float*)d_in[3];
    const float* weight_H  = (const float*)d_in[4];
    const float* weight_Rn = (const float*)d_in[5];
    float* out = (float*)d_out;

    nn_kernel<<<18, 32>>>(in_H, out_H, grid_H);
    fused_kernel<<<NB_WH + NB_RN, 256>>>(out_H, grid_Rn, weight_H, weight_Rn, out);
}

// round 5
// speedup vs baseline: 2.1832x; 1.1832x over previous
#include <cuda_runtime.h>
#include <cuda_bf16.h>

#define O_CH  256
#define C_IN  128
#define KH_N  24
#define N_IN  24
#define N_OUT 24
#define KS    5
#define VOL   (KS*KS*KS)                          // 125
#define WH_SIZE ((size_t)O_CH*N_IN*C_IN*N_OUT)    // 18,874,368
#define A_GRP 8                                   // a's per gather block
#define NB_WH (O_CH * (N_IN / A_GRP))             // 768 gather blocks
#define NB_RN O_CH                                // 256 wrn blocks

// ---------------------------------------------------------------------------
// Single fused kernel.
// Blocks [0, NB_WH): wH gather. Per block: (o, 8 consecutive a's).
//   - stage weight_H[o] (12 KB) + rotation matrices in smem
//   - 192 threads compute the 8x24 nn indices inline (cheap, smem-fed)
//   - each warp: load row into lanes 0..23, emit 8 permuted rows via SHFL
// Blocks [NB_WH, NB_WH+NB_RN): wRn trilinear resample (one block per o).
// ---------------------------------------------------------------------------
__global__ void __launch_bounds__(256) fused_kernel(
        const float* __restrict__ in_H,      // [24,3,3]
        const float* __restrict__ out_H,     // [24,3,3]
        const float* __restrict__ grid_H,    // [24,3,3]
        const float* __restrict__ grid_Rn,   // [3,5,5,5]
        const float* __restrict__ weight_H,  // [256,128,24]
        const float* __restrict__ weight_Rn, // [256,1,5,5,5]
        float* __restrict__ out) {
    const int idx = blockIdx.x;
    const int t = threadIdx.x;

    if (idx < NB_WH) {
        // ================= wH gather =================
        __shared__ float sw[C_IN * KH_N];     // 12 KB weights (stride 24)
        __shared__ float sOH[216], sGH[216], sIH[A_GRP * 9];
        __shared__ int   snn[A_GRP * N_OUT];  // 192 indices

        const int o  = idx / (N_IN / A_GRP);
        const int a0 = (idx % (N_IN / A_GRP)) * A_GRP;

        // stage weights (coalesced float4) + matrices
        const float4* wsrc = reinterpret_cast<const float4*>(
            weight_H + (size_t)o * C_IN * KH_N);
#pragma unroll
        for (int j = t; j < 768; j += 256)
            reinterpret_cast<float4*>(sw)[j] = wsrc[j];
        if (t < 216) { sOH[t] = out_H[t]; sGH[t] = grid_H[t]; }
        if (t < A_GRP * 9) sIH[t] = in_H[a0 * 9 + t];
        __syncthreads();

        // inline nn: thread t<192 handles (a = a0 + t/24, b = t%24)
        if (t < A_GRP * N_OUT) {
            const int al = t / N_OUT, b = t % N_OUT;
            float P[9];
#pragma unroll
            for (int i = 0; i < 3; i++)
#pragma unroll
                for (int j = 0; j < 3; j++) {
                    float s = 0.f;
#pragma unroll
                    for (int k = 0; k < 3; k++)
                        s += sOH[b * 9 + k * 3 + i] * sIH[al * 9 + k * 3 + j];
                    P[i * 3 + j] = s;
                }
            float best = -1e30f; int bi = 0;
            for (int kh = 0; kh < KH_N; kh++) {
                float s = 0.f;
#pragma unroll
                for (int i = 0; i < 9; i++) s += P[i] * sGH[kh * 9 + i];
                if (s > best) { best = s; bi = kh; }   // strict > = first max
            }
            snn[t] = bi;
        }
        __syncthreads();

        const int lane = t & 31;
        const int wrp  = t >> 5;              // 8 warps
        const int ln   = (lane < N_OUT) ? lane : 0;

        // per-lane shuffle source indices for the 8 a's
        int idxr[A_GRP];
#pragma unroll
        for (int al = 0; al < A_GRP; al++) idxr[al] = snn[al * N_OUT + ln];

        float* outo = out + ((size_t)o * N_IN + a0) * (C_IN * N_OUT);

        // each warp: rows c = wrp, wrp+8, ... (16 rows)
#pragma unroll 4
        for (int c = wrp; c < C_IN; c += 8) {
            const float wv = sw[c * KH_N + ln];
            float* rowdst = outo + c * N_OUT + lane;
#pragma unroll
            for (int al = 0; al < A_GRP; al++) {
                const float v = __shfl_sync(0xffffffffu, wv, idxr[al]);
                if (lane < N_OUT) rowdst[al * (C_IN * N_OUT)] = v;
            }
        }
    } else {
        // ================= wRn trilinear =================
        __shared__ float vol[VOL];
        __shared__ float R[216];
        __shared__ float sg[3 * VOL];
        const int o = idx - NB_WH;
        if (t < VOL) vol[t] = weight_Rn[(size_t)o * VOL + t];
        if (t < 216) R[t]   = out_H[t];
        for (int i = t; i < 3 * VOL; i += 256) sg[i] = grid_Rn[i];
        __syncthreads();

#pragma unroll
        for (int f = t; f < N_OUT * VOL; f += 256) {
            const int b = f / VOL;
            const int p = f % VOL;
            const float* Rb = R + b * 9;

            const float g0 = sg[p], g1 = sg[VOL + p], g2 = sg[2 * VOL + p];
            float cz = Rb[0] * g0 + Rb[3] * g1 + Rb[6] * g2;
            float cy = Rb[1] * g0 + Rb[4] * g1 + Rb[7] * g2;
            float cx = Rb[2] * g0 + Rb[5] * g1 + Rb[8] * g2;
            cz = (cz + 1.f) * 0.5f * (KS - 1);
            cy = (cy + 1.f) * 0.5f * (KS - 1);
            cx = (cx + 1.f) * 0.5f * (KS - 1);

            const float z0f = floorf(cz), y0f = floorf(cy), x0f = floorf(cx);
            const int z0 = (int)z0f, y0 = (int)y0f, x0 = (int)x0f;
            const float fz = cz - z0f, fy = cy - y0f, fx = cx - x0f;

            float acc = 0.f;
#pragma unroll
            for (int dz = 0; dz < 2; dz++)
#pragma unroll
                for (int dy = 0; dy < 2; dy++)
#pragma unroll
                    for (int dx = 0; dx < 2; dx++) {
                        const int iz = z0 + dz, iy = y0 + dy, ix = x0 + dx;
                        const bool valid = (iz >= 0) & (iz < KS) & (iy >= 0) & (iy < KS)
                                         & (ix >= 0) & (ix < KS);
                        const int ci = min(max(iz, 0), KS - 1) * 25
                                     + min(max(iy, 0), KS - 1) * 5
                                     + min(max(ix, 0), KS - 1);
                        const float w = (dz ? fz : 1.f - fz) * (dy ? fy : 1.f - fy)
                                      * (dx ? fx : 1.f - fx);
                        acc += (valid ? vol[ci] : 0.f) * w;
                    }

            out[WH_SIZE + (size_t)o * (N_OUT * VOL) + f] = acc;
        }
    }
}

// ---------------------------------------------------------------------------
extern "C" void kernel_launch(void* const* d_in, const int* in_sizes, int n_in,
                              void* d_out, int out_size) {
    const float* in_H      = (const float*)d_in[0];
    const float* out_H     = (const float*)d_in[1];
    const float* grid_H    = (const float*)d_in[2];
    const float* grid_Rn   = (const float*)d_in[3];
    const float* weight_H  = (const float*)d_in[4];
    const float* weight_Rn = (const float*)d_in[5];
    float* out = (float*)d_out;

    fused_kernel<<<NB_WH + NB_RN, 256>>>(
        in_H, out_H, grid_H, grid_Rn, weight_H, weight_Rn, out);
}